// round 1
// baseline (speedup 1.0000x reference)
#include <cuda_runtime.h>
#include <math.h>

// Problem constants (fixed shapes from setup_inputs)
#define BB 4
#define CC 64
#define HH 128
#define WW 128
#define DD 256
#define NN 100
#define MAXDET 10
#define HWP (HH*WW)              // 16384
#define SEG_OFF   0              // 65536 floats, layout [p][b]
#define MASK_OFF  (HWP*BB)       // 65536 floats, layout [b][p]
#define KEPT_OFF  (MASK_OFF + HWP*BB)   // 200 floats, [b][det][5]
#define VALID_OFF (KEPT_OFF + BB*MAXDET*5) // 40 floats, [b][det]

#define TILE 16
#define APAD 260                 // 256 padded to multiple of 4, not mult of 32-ish

// ---------------- device scratch (no allocations allowed) ----------------
__device__ int   g_count;
__device__ int   g_list[BB*HWP];
__device__ int   g_ibox[BB][MAXDET][4];
__device__ int   g_valid[BB][MAXDET];
__device__ float g_seg0;

// ---------------- Kernel 1: NMS per batch ----------------
__global__ void nms_kernel(const float* __restrict__ rb, float* __restrict__ out) {
    const int b = blockIdx.x;
    const int t = threadIdx.x;   // 128 threads

    __shared__ float bx[NN*5];
    __shared__ float area[NN];
    __shared__ float iou[NN*NN];
    __shared__ int   cand[NN];
    __shared__ float rv[128];
    __shared__ int   ri[128];
    __shared__ int   s_any;
    __shared__ int   idxs[MAXDET];
    __shared__ int   hasA[MAXDET];

    for (int i = t; i < NN*5; i += 128) bx[i] = rb[b*NN*5 + i];
    if (t == 0) s_any = 0;
    __syncthreads();

    if (t < NN) {
        float a = fmaxf(bx[t*5+2]-bx[t*5+0], 0.f) * fmaxf(bx[t*5+3]-bx[t*5+1], 0.f);
        area[t] = a;
        if (bx[t*5+4] > 0.2f) atomicOr(&s_any, 1);
    }
    __syncthreads();

    for (int k = t; k < NN*NN; k += 128) {
        int i = k / NN, j = k - i*NN;
        float lx = fmaxf(bx[i*5+0], bx[j*5+0]);
        float ly = fmaxf(bx[i*5+1], bx[j*5+1]);
        float rx = fminf(bx[i*5+2], bx[j*5+2]);
        float ry = fminf(bx[i*5+3], bx[j*5+3]);
        float iw = fmaxf(rx - lx, 0.f);
        float ih = fmaxf(ry - ly, 0.f);
        float inter = iw * ih;
        iou[k] = inter / (area[i] + area[j] - inter + 1e-9f);
    }
    if (t < NN) cand[t] = s_any ? (bx[t*5+4] > 0.2f ? 1 : 0) : 1;
    __syncthreads();

    // greedy loop, MAXDET iterations, block-parallel first-max argmax
    for (int it = 0; it < MAXDET; it++) {
        float sc = (t < NN && cand[t]) ? bx[t*5+4] : -INFINITY;
        rv[t] = sc; ri[t] = t;
        __syncthreads();
        for (int off = 64; off; off >>= 1) {
            if (t < off) {
                float v2 = rv[t+off]; int i2 = ri[t+off];
                if (v2 > rv[t] || (v2 == rv[t] && i2 < ri[t])) { rv[t] = v2; ri[t] = i2; }
            }
            __syncthreads();
        }
        int  bi  = ri[0];
        bool has = rv[0] > -INFINITY;
        if (t == 0) { idxs[it] = bi; hasA[it] = has ? 1 : 0; }
        if (has && t < NN) {
            if (iou[bi*NN + t] > 0.4f || t == bi) cand[t] = 0;
        }
        __syncthreads();
    }

    // write kept
    if (t < MAXDET*5) {
        int det = t / 5, k = t - det*5;
        out[KEPT_OFF + b*MAXDET*5 + t] = bx[idxs[det]*5 + k];
    }
    // write valid + integer boxes
    if (t < MAXDET) {
        int kr = idxs[t];
        float x1f = bx[kr*5+0], y1f = bx[kr*5+1];
        float x2f = bx[kr*5+2], y2f = bx[kr*5+3];
        int v = hasA[t] && (x2f - x1f >= 1.f) && (y2f - y1f >= 1.f)
                        && (s_any ? 1 : (t < 5));
        out[VALID_OFF + b*MAXDET + t] = v ? 1.f : 0.f;
        g_valid[b][t] = v;
        int x1 = (int)floorf(x1f + 0.5f); x1 = min(max(x1, 0), WW);
        int y1 = (int)floorf(y1f + 0.5f); y1 = min(max(y1, 0), HH);
        int x2 = (int)floorf(x2f + 0.5f); x2 = min(max(x2, 0), WW);
        int y2 = (int)floorf(y2f + 0.5f); y2 = min(max(y2, 0), HH);
        g_ibox[b][t][0] = x1; g_ibox[b][t][1] = y1;
        g_ibox[b][t][2] = x2; g_ibox[b][t][3] = y2;
    }
    if (b == 0 && t == 0) g_count = 0;
}

// ---------------- Kernel 2: seg value for all-zero pixels ----------------
__global__ void seg0_kernel(const float* __restrict__ b1, const float* __restrict__ W2,
                            const float* __restrict__ b2, const float* __restrict__ W3,
                            const float* __restrict__ b3) {
    __shared__ float h1c[DD];
    __shared__ float red[DD];
    int t = threadIdx.x;
    h1c[t] = fmaxf(b1[t], 0.f);
    __syncthreads();
    float acc = b2[t];
    for (int d = 0; d < DD; d++) acc += h1c[d] * W2[d*DD + t];
    float h2 = fmaxf(acc, 0.f);
    red[t] = h2 * W3[t];
    __syncthreads();
    for (int off = 128; off; off >>= 1) {
        if (t < off) red[t] += red[t + off];
        __syncthreads();
    }
    if (t == 0) g_seg0 = red[0] + b3[0];
}

// ---------------- Kernel 3: mask + default seg + compact inside pixels ----
__global__ void mask_kernel(float* __restrict__ out) {
    int gid = blockIdx.x * blockDim.x + threadIdx.x;   // 0 .. B*H*W-1
    if (gid >= BB*HWP) return;
    int b = gid >> 14;
    int p = gid & (HWP - 1);
    int h = p >> 7;
    int w = p & (WW - 1);
    bool inside = false;
    #pragma unroll
    for (int k = 0; k < MAXDET; k++) {
        if (g_valid[b][k]) {
            int x1 = g_ibox[b][k][0], y1 = g_ibox[b][k][1];
            int x2 = g_ibox[b][k][2], y2 = g_ibox[b][k][3];
            inside |= (w >= x1 && w < x2 && h >= y1 && h < y2);
        }
    }
    out[MASK_OFF + gid] = inside ? 0.f : 1.f;
    out[SEG_OFF + p*BB + b] = g_seg0;
    if (inside) {
        int pos = atomicAdd(&g_count, 1);
        g_list[pos] = gid;
    }
}

// ---------------- Kernel 4: sparse per-pixel MLP ----------------
__global__ void __launch_bounds__(256) mlp_kernel(
        const float* __restrict__ x,
        const float* __restrict__ W_sem, const float* __restrict__ b_sem,
        const float* __restrict__ W1, const float* __restrict__ b1,
        const float* __restrict__ W2, const float* __restrict__ b2,
        const float* __restrict__ W3, const float* __restrict__ b3,
        float* __restrict__ out) {
    __shared__ float sx[TILE][CC];
    __shared__ float sa[TILE][APAD];
    __shared__ float sb[TILE][APAD];
    __shared__ int   spix[TILE];

    const int t = threadIdx.x;         // 256 threads, t == feature index
    const int count = g_count;
    const int ntiles = (count + TILE - 1) / TILE;

    for (int tile = blockIdx.x; tile < ntiles; tile += gridDim.x) {
        int base = tile * TILE;
        int rem  = count - base; if (rem > TILE) rem = TILE;

        if (t < TILE) {
            int slot = (t < rem) ? base + t : base;
            spix[t] = g_list[slot];
        }
        __syncthreads();

        // gather x for TILE pixels
        for (int i = t; i < TILE*CC; i += 256) {
            int p = i >> 6, c = i & (CC - 1);
            int pk = spix[p];
            int b = pk >> 14, pp = pk & (HWP - 1);
            sx[p][c] = x[((b << 6) + c) * HWP + pp];
        }
        __syncthreads();

        float acc[TILE];

        // seman: out feature d = t, reduce over 64 channels
        #pragma unroll
        for (int p = 0; p < TILE; p++) acc[p] = b_sem[t];
        for (int c = 0; c < CC; c += 4) {
            float w0 = W_sem[(c+0)*DD + t];
            float w1 = W_sem[(c+1)*DD + t];
            float w2 = W_sem[(c+2)*DD + t];
            float w3 = W_sem[(c+3)*DD + t];
            #pragma unroll
            for (int p = 0; p < TILE; p++) {
                float4 v = *(const float4*)&sx[p][c];
                acc[p] += v.x*w0 + v.y*w1 + v.z*w2 + v.w*w3;
            }
        }
        #pragma unroll
        for (int p = 0; p < TILE; p++) sa[p][t] = acc[p];
        __syncthreads();

        // h1 = relu(sa @ W1 + b1)
        #pragma unroll
        for (int p = 0; p < TILE; p++) acc[p] = b1[t];
        for (int d = 0; d < DD; d += 4) {
            float w0 = W1[(d+0)*DD + t];
            float w1 = W1[(d+1)*DD + t];
            float w2 = W1[(d+2)*DD + t];
            float w3 = W1[(d+3)*DD + t];
            #pragma unroll
            for (int p = 0; p < TILE; p++) {
                float4 v = *(const float4*)&sa[p][d];
                acc[p] += v.x*w0 + v.y*w1 + v.z*w2 + v.w*w3;
            }
        }
        #pragma unroll
        for (int p = 0; p < TILE; p++) sb[p][t] = fmaxf(acc[p], 0.f);
        __syncthreads();

        // h2 = relu(sb @ W2 + b2)
        #pragma unroll
        for (int p = 0; p < TILE; p++) acc[p] = b2[t];
        for (int d = 0; d < DD; d += 4) {
            float w0 = W2[(d+0)*DD + t];
            float w1 = W2[(d+1)*DD + t];
            float w2 = W2[(d+2)*DD + t];
            float w3 = W2[(d+3)*DD + t];
            #pragma unroll
            for (int p = 0; p < TILE; p++) {
                float4 v = *(const float4*)&sb[p][d];
                acc[p] += v.x*w0 + v.y*w1 + v.z*w2 + v.w*w3;
            }
        }
        #pragma unroll
        for (int p = 0; p < TILE; p++) sa[p][t] = fmaxf(acc[p], 0.f);
        __syncthreads();

        // seg = h2 @ W3 + b3[0]
        if (t < rem) {
            float s = 0.f;
            for (int j = 0; j < DD; j++) s += sa[t][j] * W3[j];
            int pk = spix[t];
            int b = pk >> 14, pp = pk & (HWP - 1);
            out[SEG_OFF + pp*BB + b] = s + b3[0];
        }
        __syncthreads();
    }
}

// ---------------- launch ----------------
extern "C" void kernel_launch(void* const* d_in, const int* in_sizes, int n_in,
                              void* d_out, int out_size) {
    (void)in_sizes; (void)n_in; (void)out_size;
    const float* x     = (const float*)d_in[0];
    const float* rb    = (const float*)d_in[1];
    const float* W_sem = (const float*)d_in[2];
    const float* b_sem = (const float*)d_in[3];
    const float* W1    = (const float*)d_in[4];
    const float* b1    = (const float*)d_in[5];
    const float* W2    = (const float*)d_in[6];
    const float* b2    = (const float*)d_in[7];
    const float* W3    = (const float*)d_in[8];
    const float* b3    = (const float*)d_in[9];
    float* out = (float*)d_out;

    nms_kernel<<<BB, 128>>>(rb, out);
    seg0_kernel<<<1, 256>>>(b1, W2, b2, W3, b3);
    mask_kernel<<<(BB*HWP)/256, 256>>>(out);
    mlp_kernel<<<1024, 256>>>(x, W_sem, b_sem, W1, b1, W2, b2, W3, b3, out);
}

// round 2
// speedup vs baseline: 1.2749x; 1.2749x over previous
#include <cuda_runtime.h>
#include <math.h>

// Problem constants (fixed shapes from setup_inputs)
#define BB 4
#define CC 64
#define HH 128
#define WW 128
#define DD 256
#define NN 100
#define MAXDET 10
#define HWP (HH*WW)              // 16384
#define SEG_OFF   0
#define MASK_OFF  (HWP*BB)
#define KEPT_OFF  (MASK_OFF + HWP*BB)
#define VALID_OFF (KEPT_OFF + BB*MAXDET*5)

#define TP 8                     // pixels per tile
#define RPAD 12                  // padded row length (48B, 16B aligned)

// ---------------- device scratch ----------------
__device__ int   g_count;
__device__ int   g_list[BB*HWP];
__device__ int   g_ibox[BB][MAXDET][4];
__device__ int   g_valid[BB][MAXDET];
__device__ float g_seg0;

typedef unsigned long long ull;

// ---------------- packed f32x2 helpers (sm_103a) ----------------
__device__ __forceinline__ ull fma2(ull a, ull b, ull c) {
    ull d;
    asm("fma.rn.f32x2 %0, %1, %2, %3;" : "=l"(d) : "l"(a), "l"(b), "l"(c));
    return d;
}
__device__ __forceinline__ ull add2(ull a, ull b) {
    ull d;
    asm("add.rn.f32x2 %0, %1, %2;" : "=l"(d) : "l"(a), "l"(b));
    return d;
}
__device__ __forceinline__ ull pack2(float x) {
    unsigned u = __float_as_uint(x);
    ull r;
    asm("mov.b64 %0, {%1, %2};" : "=l"(r) : "r"(u), "r"(u));
    return r;
}
__device__ __forceinline__ void unpack2(ull v, float& lo, float& hi) {
    unsigned a, b;
    asm("mov.b64 {%0, %1}, %2;" : "=r"(a), "=r"(b) : "l"(v));
    lo = __uint_as_float(a);
    hi = __uint_as_float(b);
}

// ---------------- Kernel 1: NMS per batch ----------------
__global__ void nms_kernel(const float* __restrict__ rb, float* __restrict__ out) {
    const int b = blockIdx.x;
    const int t = threadIdx.x;   // 128 threads

    __shared__ float bx[NN*5];
    __shared__ float area[NN];
    __shared__ float iou[NN*NN];
    __shared__ int   cand[NN];
    __shared__ float rv[128];
    __shared__ int   ri[128];
    __shared__ int   s_any;
    __shared__ int   idxs[MAXDET];
    __shared__ int   hasA[MAXDET];

    for (int i = t; i < NN*5; i += 128) bx[i] = rb[b*NN*5 + i];
    if (t == 0) s_any = 0;
    __syncthreads();

    if (t < NN) {
        float a = fmaxf(bx[t*5+2]-bx[t*5+0], 0.f) * fmaxf(bx[t*5+3]-bx[t*5+1], 0.f);
        area[t] = a;
        if (bx[t*5+4] > 0.2f) atomicOr(&s_any, 1);
    }
    __syncthreads();

    for (int k = t; k < NN*NN; k += 128) {
        int i = k / NN, j = k - i*NN;
        float lx = fmaxf(bx[i*5+0], bx[j*5+0]);
        float ly = fmaxf(bx[i*5+1], bx[j*5+1]);
        float rx = fminf(bx[i*5+2], bx[j*5+2]);
        float ry = fminf(bx[i*5+3], bx[j*5+3]);
        float iw = fmaxf(rx - lx, 0.f);
        float ih = fmaxf(ry - ly, 0.f);
        float inter = iw * ih;
        iou[k] = inter / (area[i] + area[j] - inter + 1e-9f);
    }
    if (t < NN) cand[t] = s_any ? (bx[t*5+4] > 0.2f ? 1 : 0) : 1;
    __syncthreads();

    for (int it = 0; it < MAXDET; it++) {
        float sc = (t < NN && cand[t]) ? bx[t*5+4] : -INFINITY;
        rv[t] = sc; ri[t] = t;
        __syncthreads();
        for (int off = 64; off; off >>= 1) {
            if (t < off) {
                float v2 = rv[t+off]; int i2 = ri[t+off];
                if (v2 > rv[t] || (v2 == rv[t] && i2 < ri[t])) { rv[t] = v2; ri[t] = i2; }
            }
            __syncthreads();
        }
        int  bi  = ri[0];
        bool has = rv[0] > -INFINITY;
        if (t == 0) { idxs[it] = bi; hasA[it] = has ? 1 : 0; }
        if (has && t < NN) {
            if (iou[bi*NN + t] > 0.4f || t == bi) cand[t] = 0;
        }
        __syncthreads();
    }

    if (t < MAXDET*5) {
        int det = t / 5, k = t - det*5;
        out[KEPT_OFF + b*MAXDET*5 + t] = bx[idxs[det]*5 + k];
    }
    if (t < MAXDET) {
        int kr = idxs[t];
        float x1f = bx[kr*5+0], y1f = bx[kr*5+1];
        float x2f = bx[kr*5+2], y2f = bx[kr*5+3];
        int v = hasA[t] && (x2f - x1f >= 1.f) && (y2f - y1f >= 1.f)
                        && (s_any ? 1 : (t < 5));
        out[VALID_OFF + b*MAXDET + t] = v ? 1.f : 0.f;
        g_valid[b][t] = v;
        int x1 = (int)floorf(x1f + 0.5f); x1 = min(max(x1, 0), WW);
        int y1 = (int)floorf(y1f + 0.5f); y1 = min(max(y1, 0), HH);
        int x2 = (int)floorf(x2f + 0.5f); x2 = min(max(x2, 0), WW);
        int y2 = (int)floorf(y2f + 0.5f); y2 = min(max(y2, 0), HH);
        g_ibox[b][t][0] = x1; g_ibox[b][t][1] = y1;
        g_ibox[b][t][2] = x2; g_ibox[b][t][3] = y2;
    }
    if (b == 0 && t == 0) g_count = 0;
}

// ---------------- Kernel 2: seg value for all-zero pixels ----------------
__global__ void seg0_kernel(const float* __restrict__ b1, const float* __restrict__ W2,
                            const float* __restrict__ b2, const float* __restrict__ W3,
                            const float* __restrict__ b3) {
    __shared__ float h1c[DD];
    __shared__ float red[DD];
    int t = threadIdx.x;
    h1c[t] = fmaxf(b1[t], 0.f);
    __syncthreads();
    float acc = b2[t];
    for (int d = 0; d < DD; d++) acc += h1c[d] * W2[d*DD + t];
    float h2 = fmaxf(acc, 0.f);
    red[t] = h2 * W3[t];
    __syncthreads();
    for (int off = 128; off; off >>= 1) {
        if (t < off) red[t] += red[t + off];
        __syncthreads();
    }
    if (t == 0) g_seg0 = red[0] + b3[0];
}

// ---------------- Kernel 3: mask + default seg + compact ----------------
__global__ void mask_kernel(float* __restrict__ out) {
    int gid = blockIdx.x * blockDim.x + threadIdx.x;
    if (gid >= BB*HWP) return;
    int b = gid >> 14;
    int p = gid & (HWP - 1);
    int h = p >> 7;
    int w = p & (WW - 1);
    bool inside = false;
    #pragma unroll
    for (int k = 0; k < MAXDET; k++) {
        if (g_valid[b][k]) {
            int x1 = g_ibox[b][k][0], y1 = g_ibox[b][k][1];
            int x2 = g_ibox[b][k][2], y2 = g_ibox[b][k][3];
            inside |= (w >= x1 && w < x2 && h >= y1 && h < y2);
        }
    }
    out[MASK_OFF + gid] = inside ? 0.f : 1.f;
    out[SEG_OFF + p*BB + b] = g_seg0;
    if (inside) {
        int pos = atomicAdd(&g_count, 1);
        g_list[pos] = gid;
    }
}

// ---------------- layer helper: 256->256, packed f32x2, 2-way k-split ----
// in:  transposed activations in[d][pixel], RPAD-padded rows
// out: transposed activations out[t][pixel]
__device__ __forceinline__ void layer_k(
        const float* __restrict__ Wm, const float* __restrict__ bias,
        const float (*in)[RPAD], float (*outp)[RPAD], float (*sP)[TP],
        int t, int kp, int Ktot, bool relu) {
    ull acc0, acc1, acc2, acc3;
    if (kp == 0) {
        ull bb = pack2(bias[t]);
        acc0 = bb; acc1 = bb; acc2 = bb; acc3 = bb;
    } else {
        acc0 = 0; acc1 = 0; acc2 = 0; acc3 = 0;
    }
    const int kh = Ktot >> 1;
    const int k0 = kp * kh;
    #pragma unroll 8
    for (int d = k0; d < k0 + kh; d++) {
        ull w2 = pack2(Wm[d*DD + t]);
        ulonglong2 v0 = *(const ulonglong2*)&in[d][0];
        ulonglong2 v1 = *(const ulonglong2*)&in[d][4];
        acc0 = fma2(w2, v0.x, acc0);
        acc1 = fma2(w2, v0.y, acc1);
        acc2 = fma2(w2, v1.x, acc2);
        acc3 = fma2(w2, v1.y, acc3);
    }
    if (kp == 1) {
        ulonglong2* row = (ulonglong2*)&sP[t][0];
        row[0] = make_ulonglong2(acc0, acc1);
        row[1] = make_ulonglong2(acc2, acc3);
    }
    __syncthreads();
    if (kp == 0) {
        ulonglong2* row = (ulonglong2*)&sP[t][0];
        ulonglong2 q0 = row[0], q1 = row[1];
        acc0 = add2(acc0, q0.x);
        acc1 = add2(acc1, q0.y);
        acc2 = add2(acc2, q1.x);
        acc3 = add2(acc3, q1.y);
        float v[8];
        unpack2(acc0, v[0], v[1]);
        unpack2(acc1, v[2], v[3]);
        unpack2(acc2, v[4], v[5]);
        unpack2(acc3, v[6], v[7]);
        if (relu) {
            #pragma unroll
            for (int i = 0; i < 8; i++) v[i] = fmaxf(v[i], 0.f);
        }
        #pragma unroll
        for (int i = 0; i < 8; i++) outp[t][i] = v[i];
    }
    __syncthreads();
}

// ---------------- Kernel 4: sparse per-pixel MLP (packed f32x2) ----------
__global__ void __launch_bounds__(512) mlp_kernel(
        const float* __restrict__ x,
        const float* __restrict__ W_sem, const float* __restrict__ b_sem,
        const float* __restrict__ W1, const float* __restrict__ b1,
        const float* __restrict__ W2, const float* __restrict__ b2,
        const float* __restrict__ W3, const float* __restrict__ b3,
        float* __restrict__ out) {
    __shared__ __align__(16) float sx[CC][RPAD];   // x transposed [c][pixel]
    __shared__ __align__(16) float sA[DD][RPAD];   // activations ping
    __shared__ __align__(16) float sB[DD][RPAD];   // activations pong
    __shared__ __align__(16) float sP[DD][TP];     // k-split partials
    __shared__ int spix[TP];

    const int t  = threadIdx.x & 255;   // output feature
    const int kp = threadIdx.x >> 8;    // k partition (0/1)
    const int count = g_count;
    const int ntiles = (count + TP - 1) / TP;

    for (int tile = blockIdx.x; tile < ntiles; tile += gridDim.x) {
        const int base = tile * TP;
        const int rem  = min(count - base, TP);

        if (threadIdx.x < TP) {
            spix[threadIdx.x] = g_list[threadIdx.x < rem ? base + threadIdx.x : base];
        }
        __syncthreads();

        // gather x transposed: sx[c][p]
        for (int i = threadIdx.x; i < TP*CC; i += 512) {
            int c = i >> 3, p = i & (TP - 1);
            int pk = spix[p];
            int b = pk >> 14, pp = pk & (HWP - 1);
            sx[c][p] = x[((b << 6) + c) * HWP + pp];
        }
        __syncthreads();

        // seman (64 -> 256, no relu) : sx -> sA
        layer_k(W_sem, b_sem, sx, sA, sP, t, kp, CC, false);
        // layer1 (256 -> 256, relu)  : sA -> sB
        layer_k(W1, b1, sA, sB, sP, t, kp, DD, true);
        // layer2 (256 -> 256, relu)  : sB -> sA
        layer_k(W2, b2, sB, sA, sP, t, kp, DD, true);

        // final: seg[p] = sA[:, p] . W3 + b3[0]; one warp per pixel
        {
            int w = threadIdx.x >> 5;   // warp id 0..15
            int l = threadIdx.x & 31;
            if (w < rem) {
                float s = 0.f;
                #pragma unroll
                for (int j = l; j < DD; j += 32) s += sA[j][w] * W3[j];
                #pragma unroll
                for (int off = 16; off; off >>= 1)
                    s += __shfl_down_sync(0xffffffffu, s, off);
                if (l == 0) {
                    int pk = spix[w];
                    int b = pk >> 14, pp = pk & (HWP - 1);
                    out[SEG_OFF + pp*BB + b] = s + b3[0];
                }
            }
        }
        __syncthreads();
    }
}

// ---------------- launch ----------------
extern "C" void kernel_launch(void* const* d_in, const int* in_sizes, int n_in,
                              void* d_out, int out_size) {
    (void)in_sizes; (void)n_in; (void)out_size;
    const float* x     = (const float*)d_in[0];
    const float* rb    = (const float*)d_in[1];
    const float* W_sem = (const float*)d_in[2];
    const float* b_sem = (const float*)d_in[3];
    const float* W1    = (const float*)d_in[4];
    const float* b1    = (const float*)d_in[5];
    const float* W2    = (const float*)d_in[6];
    const float* b2    = (const float*)d_in[7];
    const float* W3    = (const float*)d_in[8];
    const float* b3    = (const float*)d_in[9];
    float* out = (float*)d_out;

    nms_kernel<<<BB, 128>>>(rb, out);
    seg0_kernel<<<1, 256>>>(b1, W2, b2, W3, b3);
    mask_kernel<<<(BB*HWP)/256, 256>>>(out);
    // worst case: 10 boxes * 17x17 px * 4 batches = 11560 px -> 1445 tiles
    mlp_kernel<<<1445, 512>>>(x, W_sem, b_sem, W1, b1, W2, b2, W3, b3, out);
}